// round 10
// baseline (speedup 1.0000x reference)
#include <cuda_runtime.h>
#include <cuda_bf16.h>
#include <cuda_fp16.h>
#include <cstdint>

// EGCL_A2V — bf16 HMMA + ldmatrix, 224-row tiles (14 warps), dynamic tiles.
// Fast path: warp-private pipeline, x1 packed bf16 in regs, 2 __syncthreads
// per tile. Slow path: R8-proven body generalized to TILE=224.

#define NF 128
#define H  128
#define C  3
#define B_MAX 256
#define THREADS 448
#define NW 14
#define TILE 224
#define NBLK 148
#define PAD 136
#define WSTRIDE (128*PAD)

#define SMEM_SW 0
#define SMEM_SA 104448
#define SMEM_F  165376
#define SMEM_TOTAL 203264

// float-region layout (indices into float*)
#define F_WR    0
#define F_BE2   128
#define F_BC1   256
#define F_WC2   384
#define F_SRAD  512          // [224][3] -> 672
#define F_SDIFF 1184         // [224][9] -> 2016
#define F_SSM   3200         // [3][224] -> 672
#define F_SWP   3872         // [3][14][128] -> 5376
#define F_SBID  9248         // int[224]

__device__ float g_V1[B_MAX * C * H];
__device__ float g_aggM[B_MAX * C * H];
__device__ float g_aggT[B_MAX * 9];
__device__ float g_cnt[B_MAX];
__device__ unsigned g_tile;
__device__ __align__(16) __nv_bfloat16 g_Wimg[3 * WSTRIDE];

// ---------------- helpers ----------------
__device__ __forceinline__ float silu_p(float x) { return x / (1.0f + __expf(-x)); }

__device__ __forceinline__ float2 silu2(float f0, float f1) {
    __half2 h  = __floats2half2_rn(f0, f1);
    __half2 hx = __hmul2(h, __float2half2_rn(0.5f));
    uint32_t hu = *reinterpret_cast<uint32_t*>(&hx);
    uint32_t tu;
    asm("tanh.approx.f16x2 %0, %1;" : "=r"(tu) : "r"(hu));
    __half2 t = *reinterpret_cast<__half2*>(&tu);
    __half2 s = __hfma2(hx, t, hx);
    return __half22float2(s);
}
__device__ __forceinline__ uint32_t pack_bf16(float lo, float hi) {
    uint32_t r;
    asm("cvt.rn.bf16x2.f32 %0, %1, %2;" : "=r"(r) : "f"(hi), "f"(lo));
    return r;
}
__device__ __forceinline__ float2 unpack_bf16(uint32_t u) {
    __nv_bfloat162 h = *reinterpret_cast<__nv_bfloat162*>(&u);
    return __bfloat1622float2(h);
}
__device__ __forceinline__ uint32_t smem_u32(const void* p) {
    uint32_t a;
    asm("{ .reg .u64 t; cvta.to.shared.u64 t, %1; cvt.u32.u64 %0, t; }" : "=r"(a) : "l"(p));
    return a;
}
__device__ __forceinline__ void ldsm_x4(uint32_t* r, uint32_t addr) {
    asm volatile("ldmatrix.sync.aligned.m8n8.x4.shared.b16 {%0,%1,%2,%3}, [%4];"
                 : "=r"(r[0]), "=r"(r[1]), "=r"(r[2]), "=r"(r[3]) : "r"(addr));
}
__device__ __forceinline__ void mma16816(float* d,
        uint32_t a0, uint32_t a1, uint32_t a2, uint32_t a3,
        uint32_t b0, uint32_t b1) {
    asm volatile(
        "mma.sync.aligned.m16n8k16.row.col.f32.bf16.bf16.f32 "
        "{%0,%1,%2,%3}, {%4,%5,%6,%7}, {%8,%9}, {%0,%1,%2,%3};"
        : "+f"(d[0]), "+f"(d[1]), "+f"(d[2]), "+f"(d[3])
        : "r"(a0), "r"(a1), "r"(a2), "r"(a3), "r"(b0), "r"(b1));
}
__device__ __forceinline__ void gemm128(uint32_t aAddr, uint32_t bAddr, float* acc) {
#pragma unroll 2
    for (int ks = 0; ks < 8; ks++) {
        uint32_t A[4];
        ldsm_x4(A, aAddr + ks * 32);
#pragma unroll
        for (int ntp = 0; ntp < 8; ntp++) {
            uint32_t Bf[4];
            ldsm_x4(Bf, bAddr + ntp * (16 * PAD * 2) + ks * 32);
            mma16816(acc + ntp * 8,     A[0], A[1], A[2], A[3], Bf[0], Bf[1]);
            mma16816(acc + ntp * 8 + 4, A[0], A[1], A[2], A[3], Bf[2], Bf[3]);
        }
    }
}

// ---------------------------------------------------------------------------
__global__ void prep_img(const float* __restrict__ We1,
                         const float* __restrict__ We2,
                         const float* __restrict__ Wc1,
                         __nv_bfloat16* __restrict__ gW) {
    int w = blockIdx.x >> 7, k = blockIdx.x & 127, n = threadIdx.x;
    const float* W = (w == 0) ? We1 : (w == 1) ? We2 : Wc1;
    gW[w * WSTRIDE + n * PAD + k] = __float2bfloat16(W[k * H + n]);
}

// ---------------------------------------------------------------------------
__global__ void prep_V1(const float* __restrict__ vnf,
                        const float* __restrict__ We1,
                        const float* __restrict__ be1) {
    __shared__ float sv[NF];
    int h = threadIdx.x, bc = blockIdx.x;
    int b = bc / C, c = bc % C;
    sv[h] = vnf[(b * NF + h) * C + c];
    __syncthreads();
    const float* w = We1 + NF * H;
    float a0 = 0.f, a1 = 0.f, a2 = 0.f, a3 = 0.f;
#pragma unroll 8
    for (int f = 0; f < NF; f += 4) {
        a0 = fmaf(sv[f],     __ldg(&w[(f)     * H + h]), a0);
        a1 = fmaf(sv[f + 1], __ldg(&w[(f + 1) * H + h]), a1);
        a2 = fmaf(sv[f + 2], __ldg(&w[(f + 2) * H + h]), a2);
        a3 = fmaf(sv[f + 3], __ldg(&w[(f + 3) * H + h]), a3);
    }
    g_V1[bc * H + h] = be1[h] + ((a0 + a1) + (a2 + a3));
    g_aggM[bc * H + h] = 0.0f;
    if (bc == 0) {
        for (int i = h; i < B_MAX * 9; i += blockDim.x) g_aggT[i] = 0.0f;
        for (int i = h; i < B_MAX; i += blockDim.x) g_cnt[i] = 0.0f;
        if (h == 0) g_tile = 0u;
    }
}

// ---------------------------------------------------------------------------
__global__ void __launch_bounds__(THREADS, 1)
main_kernel(const float* __restrict__ node_feat,
            const float* __restrict__ coord,
            const float* __restrict__ vcoord,
            const int*   __restrict__ batch,
            const float* __restrict__ We1,
            const float* __restrict__ be2,
            const float* __restrict__ bc1,
            const float* __restrict__ Wc2,
            int N) {
    extern __shared__ __align__(16) char smem[];
    __nv_bfloat16* sW = (__nv_bfloat16*)(smem + SMEM_SW);
    __nv_bfloat16* sA = (__nv_bfloat16*)(smem + SMEM_SA);
    float* sf = (float*)(smem + SMEM_F);
    float* swr   = sf + F_WR;
    float* sbe2  = sf + F_BE2;
    float* sbc1  = sf + F_BC1;
    float* swc2  = sf + F_WC2;
    float* srad  = sf + F_SRAD;
    float* sdiff = sf + F_SDIFF;
    float* ssm   = sf + F_SSM;
    float* swp   = sf + F_SWP;
    int*   sbid  = (int*)(sf + F_SBID);
    __shared__ int s_tile;

    const int tid = threadIdx.x, lane = tid & 31, warp = tid >> 5;

    {   // weights -> smem
        const uint4* src = (const uint4*)g_Wimg;
        uint4* dst = (uint4*)sW;
        for (int i = tid; i < 3 * WSTRIDE * 2 / 16; i += THREADS) dst[i] = src[i];
    }
    if (tid < 128) {
        swr[tid]  = We1[256 * H + tid];
        sbe2[tid] = be2[tid];
        sbc1[tid] = bc1[tid];
        swc2[tid] = Wc2[tid];
    }
    __syncthreads();

    const uint32_t sA_u = smem_u32(sA);
    const uint32_t sW_u = smem_u32(sW);
    const uint32_t aAddr = sA_u +
        (((warp * 16 + (lane & 15)) * PAD + (lane >> 4) * 8) << 1);
    const uint32_t bRel =
        (((((lane >> 4) & 1) * 8 + (lane & 7)) * PAD + ((lane >> 3) & 1) * 8) << 1);
    const uint32_t bAddr0 = sW_u + bRel;
    const uint32_t bAddr1 = bAddr0 + WSTRIDE * 2;
    const uint32_t bAddr2 = bAddr1 + WSTRIDE * 2;
    const int r0 = warp * 16 + (lane >> 2), r1 = r0 + 8;

    const int ntiles = (N + TILE - 1) / TILE;
    for (;;) {
        if (tid == 0) s_tile = (int)atomicAdd(&g_tile, 1u);
        __syncthreads();                       // B1 (fences prev-tile agg too)
        const int t = s_tile;
        if (t >= ntiles) break;
        const int base = t * TILE;

        const bool tileFull = (base + TILE <= N);
        const int bFirst = __ldg(&batch[base]);
        const int bLast  = __ldg(&batch[min(base + TILE - 1, N - 1)]);
        const bool fast  = tileFull && (bFirst == bLast) && bFirst >= 0;
        const int b0t = bFirst < 0 ? 0 : bFirst;

        if (fast) {
            // ============ FAST PATH: warp-private, packed x1 ================
            {   // own-rows load
                int r = warp * 16 + (lane >> 1), cb = (lane & 1) * 64;
                int n = base + r;
                const float4* nf = (const float4*)(node_feat + (size_t)n * NF + cb);
                __nv_bfloat16* dst = sA + r * PAD + cb;
#pragma unroll
                for (int q = 0; q < 16; q++) {
                    float4 v = __ldg(&nf[q]);
                    *(uint32_t*)(dst + q * 4)     = pack_bf16(v.x, v.y);
                    *(uint32_t*)(dst + q * 4 + 2) = pack_bf16(v.z, v.w);
                }
                if (lane < 16) {
                    int m = warp * 16 + lane, nn = base + m;
                    float cx = coord[nn * 3 + 0], cy = coord[nn * 3 + 1], cz = coord[nn * 3 + 2];
#pragma unroll
                    for (int cc = 0; cc < C; cc++) {
                        float dx = __ldg(&vcoord[(b0t * 3 + 0) * C + cc]) - cx;
                        float dy = __ldg(&vcoord[(b0t * 3 + 1) * C + cc]) - cy;
                        float dz = __ldg(&vcoord[(b0t * 3 + 2) * C + cc]) - cz;
                        sdiff[m * 9 + cc * 3 + 0] = dx;
                        sdiff[m * 9 + cc * 3 + 1] = dy;
                        sdiff[m * 9 + cc * 3 + 2] = dz;
                        srad[m * 3 + cc] = sqrtf(dx * dx + dy * dy + dz * dz);
                    }
                }
            }
            if (tid == 0) atomicAdd(&g_cnt[b0t], (float)TILE);
            __syncwarp();

            // GEMM1: X1 = nf @ We1a^T -> packed bf16 (frees 32 regs)
            uint32_t xp[32];
            {
                float x1[64];
#pragma unroll
                for (int i = 0; i < 64; i++) x1[i] = 0.f;
                gemm128(aAddr, bAddr0, x1);
#pragma unroll
                for (int nt = 0; nt < 16; nt++) {
                    xp[nt * 2 + 0] = pack_bf16(x1[nt * 4 + 0], x1[nt * 4 + 1]);
                    xp[nt * 2 + 1] = pack_bf16(x1[nt * 4 + 2], x1[nt * 4 + 3]);
                }
            }
            __syncwarp();   // sA(nf own rows) consumed by this warp's GEMM1

#pragma unroll 1
            for (int c = 0; c < C; c++) {
                float rad0 = srad[r0 * 3 + c], rad1 = srad[r1 * 3 + c];
                const float* v1p = g_V1 + (b0t * C + c) * H;

                // EpA: m1 = silu(x1 + V1 + rad*wr) -> sA (own rows)
#pragma unroll
                for (int nt = 0; nt < 16; nt++) {
                    int c0 = nt * 8 + (lane & 3) * 2;
                    float2 xv0 = unpack_bf16(xp[nt * 2 + 0]);
                    float2 xv1 = unpack_bf16(xp[nt * 2 + 1]);
                    float2 vv = __ldg((const float2*)(v1p + c0));
                    float w0 = swr[c0], w1 = swr[c0 + 1];
                    float2 u0 = silu2(xv0.x + vv.x + rad0 * w0, xv0.y + vv.y + rad0 * w1);
                    float2 u1 = silu2(xv1.x + vv.x + rad1 * w0, xv1.y + vv.y + rad1 * w1);
                    *(uint32_t*)(sA + r0 * PAD + c0) = pack_bf16(u0.x, u0.y);
                    *(uint32_t*)(sA + r1 * PAD + c0) = pack_bf16(u1.x, u1.y);
                }
                __syncwarp();

                // GEMM2: M2pre = m1 @ We2^T
                float acc[64];
#pragma unroll
                for (int i = 0; i < 64; i++) acc[i] = 0.f;
                gemm128(aAddr, bAddr1, acc);
                __syncwarp();

                // EpB: m2 -> sA (own rows) + per-warp column sums
#pragma unroll
                for (int nt = 0; nt < 16; nt++) {
                    int c0 = nt * 8 + (lane & 3) * 2;
                    float2 u0 = silu2(acc[nt * 4 + 0] + sbe2[c0], acc[nt * 4 + 1] + sbe2[c0 + 1]);
                    float2 u1 = silu2(acc[nt * 4 + 2] + sbe2[c0], acc[nt * 4 + 3] + sbe2[c0 + 1]);
                    *(uint32_t*)(sA + r0 * PAD + c0) = pack_bf16(u0.x, u0.y);
                    *(uint32_t*)(sA + r1 * PAD + c0) = pack_bf16(u1.x, u1.y);
                    float v0 = u0.x + u1.x, v1 = u0.y + u1.y;
                    v0 += __shfl_xor_sync(0xffffffffu, v0, 4);
                    v0 += __shfl_xor_sync(0xffffffffu, v0, 8);
                    v0 += __shfl_xor_sync(0xffffffffu, v0, 16);
                    v1 += __shfl_xor_sync(0xffffffffu, v1, 4);
                    v1 += __shfl_xor_sync(0xffffffffu, v1, 8);
                    v1 += __shfl_xor_sync(0xffffffffu, v1, 16);
                    if (lane < 4) {
                        swp[(c * NW + warp) * 128 + c0]     = v0;
                        swp[(c * NW + warp) * 128 + c0 + 1] = v1;
                    }
                }
                __syncwarp();

                // GEMM3: Ppre = m2 @ Wc1^T
#pragma unroll
                for (int i = 0; i < 64; i++) acc[i] = 0.f;
                gemm128(aAddr, bAddr2, acc);

                // EpC: row scalar s
                {
                    float s0 = 0.f, s1 = 0.f;
#pragma unroll
                    for (int nt = 0; nt < 16; nt++) {
                        int c0 = nt * 8 + (lane & 3) * 2;
                        float2 u0 = silu2(acc[nt * 4 + 0] + sbc1[c0], acc[nt * 4 + 1] + sbc1[c0 + 1]);
                        float2 u1 = silu2(acc[nt * 4 + 2] + sbc1[c0], acc[nt * 4 + 3] + sbc1[c0 + 1]);
                        s0 += u0.x * swc2[c0] + u0.y * swc2[c0 + 1];
                        s1 += u1.x * swc2[c0] + u1.y * swc2[c0 + 1];
                    }
                    s0 += __shfl_xor_sync(0xffffffffu, s0, 1);
                    s0 += __shfl_xor_sync(0xffffffffu, s0, 2);
                    s1 += __shfl_xor_sync(0xffffffffu, s1, 1);
                    s1 += __shfl_xor_sync(0xffffffffu, s1, 2);
                    if ((lane & 3) == 0) { ssm[c * TILE + r0] = s0; ssm[c * TILE + r1] = s1; }
                }
                __syncwarp();   // GEMM3 reads done before next EpA overwrite
            }

            __syncthreads();                   // B2: swp/ssm/sdiff visible

            if (tid < 128) {
#pragma unroll
                for (int c = 0; c < C; c++) {
                    float s = 0.f;
#pragma unroll
                    for (int w = 0; w < NW; w++) s += swp[(c * NW + w) * 128 + tid];
                    atomicAdd(&g_aggM[(b0t * C + c) * H + tid], s);
                }
            }
            if (warp < 9) {
                int c = warp / 3, d = warp % 3;
                float v = 0.f;
#pragma unroll
                for (int q = 0; q < TILE / 32; q++) {
                    int r = lane + q * 32;
                    v += sdiff[r * 9 + c * 3 + d] * ssm[c * TILE + r];
                }
                v += __shfl_xor_sync(0xffffffffu, v, 16);
                v += __shfl_xor_sync(0xffffffffu, v, 8);
                v += __shfl_xor_sync(0xffffffffu, v, 4);
                v += __shfl_xor_sync(0xffffffffu, v, 2);
                v += __shfl_xor_sync(0xffffffffu, v, 1);
                if (lane == 0) atomicAdd(&g_aggT[b0t * 9 + d * 3 + c], v);
            }
            continue;
        }

        // ================= SLOW PATH ========================================
        if (tid < TILE) {
            int m = tid, n = base + m;
            bool valid = n < N;
            int nc = valid ? n : N - 1;
            int b = valid ? batch[n] : -1;
            sbid[m] = b;
            int bb = b < 0 ? 0 : b;
            float cx = coord[nc * 3 + 0], cy = coord[nc * 3 + 1], cz = coord[nc * 3 + 2];
#pragma unroll
            for (int cc = 0; cc < C; cc++) {
                float dx = __ldg(&vcoord[(bb * 3 + 0) * C + cc]) - cx;
                float dy = __ldg(&vcoord[(bb * 3 + 1) * C + cc]) - cy;
                float dz = __ldg(&vcoord[(bb * 3 + 2) * C + cc]) - cz;
                sdiff[m * 9 + cc * 3 + 0] = dx;
                sdiff[m * 9 + cc * 3 + 1] = dy;
                sdiff[m * 9 + cc * 3 + 2] = dz;
                srad[m * 3 + cc] = sqrtf(dx * dx + dy * dy + dz * dz);
            }
        }
        {
            int r = tid >> 1, cb = (tid & 1) * 64;
            int n = base + r;
            int nc = n < N ? n : N - 1;
            const float4* nf = (const float4*)(node_feat + (size_t)nc * NF + cb);
            __nv_bfloat16* dst = sA + r * PAD + cb;
#pragma unroll
            for (int q = 0; q < 16; q++) {
                float4 v = __ldg(&nf[q]);
                *(uint32_t*)(dst + q * 4)     = pack_bf16(v.x, v.y);
                *(uint32_t*)(dst + q * 4 + 2) = pack_bf16(v.z, v.w);
            }
        }
        __syncthreads();

        if (tid == 0) {
            int cb = sbid[0]; float cl = 0.f;
            for (int r = 0; r < TILE; r++) {
                int b2 = sbid[r];
                if (b2 != cb) { if (cb >= 0) atomicAdd(&g_cnt[cb], cl); cl = 0.f; cb = b2; }
                if (b2 >= 0) cl += 1.f;
            }
            if (cb >= 0) atomicAdd(&g_cnt[cb], cl);
        }

        int bb0 = sbid[r0]; bb0 = bb0 < 0 ? 0 : bb0;
        int bb1 = sbid[r1]; bb1 = bb1 < 0 ? 0 : bb1;

        uint32_t xp[32];
        {
            float x1[64];
#pragma unroll
            for (int i = 0; i < 64; i++) x1[i] = 0.f;
            gemm128(aAddr, bAddr0, x1);
#pragma unroll
            for (int nt = 0; nt < 16; nt++) {
                xp[nt * 2 + 0] = pack_bf16(x1[nt * 4 + 0], x1[nt * 4 + 1]);
                xp[nt * 2 + 1] = pack_bf16(x1[nt * 4 + 2], x1[nt * 4 + 3]);
            }
        }
        __syncthreads();

#pragma unroll 1
        for (int c = 0; c < C; c++) {
            float rad0 = srad[r0 * 3 + c], rad1 = srad[r1 * 3 + c];
            const float* v0p = g_V1 + (bb0 * C + c) * H;
            const float* v1p = g_V1 + (bb1 * C + c) * H;
#pragma unroll
            for (int nt = 0; nt < 16; nt++) {
                int c0 = nt * 8 + (lane & 3) * 2;
                float2 xv0 = unpack_bf16(xp[nt * 2 + 0]);
                float2 xv1 = unpack_bf16(xp[nt * 2 + 1]);
                float w0 = swr[c0], w1 = swr[c0 + 1];
                float2 u0 = silu2(xv0.x + __ldg(&v0p[c0])     + rad0 * w0,
                                  xv0.y + __ldg(&v0p[c0 + 1]) + rad0 * w1);
                float2 u1 = silu2(xv1.x + __ldg(&v1p[c0])     + rad1 * w0,
                                  xv1.y + __ldg(&v1p[c0 + 1]) + rad1 * w1);
                *(uint32_t*)(sA + r0 * PAD + c0) = pack_bf16(u0.x, u0.y);
                *(uint32_t*)(sA + r1 * PAD + c0) = pack_bf16(u1.x, u1.y);
            }
            __syncthreads();

            float acc[64];
#pragma unroll
            for (int i = 0; i < 64; i++) acc[i] = 0.f;
            gemm128(aAddr, bAddr1, acc);
            __syncthreads();

#pragma unroll
            for (int nt = 0; nt < 16; nt++) {
                int c0 = nt * 8 + (lane & 3) * 2;
                float2 u0 = silu2(acc[nt * 4 + 0] + sbe2[c0], acc[nt * 4 + 1] + sbe2[c0 + 1]);
                float2 u1 = silu2(acc[nt * 4 + 2] + sbe2[c0], acc[nt * 4 + 3] + sbe2[c0 + 1]);
                *(uint32_t*)(sA + r0 * PAD + c0) = pack_bf16(u0.x, u0.y);
                *(uint32_t*)(sA + r1 * PAD + c0) = pack_bf16(u1.x, u1.y);
            }
            __syncthreads();

#pragma unroll
            for (int i = 0; i < 64; i++) acc[i] = 0.f;
            gemm128(aAddr, bAddr2, acc);

            {
                float s0 = 0.f, s1 = 0.f;
#pragma unroll
                for (int nt = 0; nt < 16; nt++) {
                    int c0 = nt * 8 + (lane & 3) * 2;
                    float2 u0 = silu2(acc[nt * 4 + 0] + sbc1[c0], acc[nt * 4 + 1] + sbc1[c0 + 1]);
                    float2 u1 = silu2(acc[nt * 4 + 2] + sbc1[c0], acc[nt * 4 + 3] + sbc1[c0 + 1]);
                    s0 += u0.x * swc2[c0] + u0.y * swc2[c0 + 1];
                    s1 += u1.x * swc2[c0] + u1.y * swc2[c0 + 1];
                }
                s0 += __shfl_xor_sync(0xffffffffu, s0, 1);
                s0 += __shfl_xor_sync(0xffffffffu, s0, 2);
                s1 += __shfl_xor_sync(0xffffffffu, s1, 1);
                s1 += __shfl_xor_sync(0xffffffffu, s1, 2);
                if ((lane & 3) == 0) { ssm[r0] = s0; ssm[r1] = s1; }
            }
            __syncthreads();

            if (tid < 128) {
                int col = tid; float a = 0.f; int cb = sbid[0];
                for (int r = 0; r < TILE; r++) {
                    int b2 = sbid[r];
                    if (b2 != cb) {
                        if (cb >= 0) atomicAdd(&g_aggM[(cb * C + c) * H + col], a);
                        a = 0.f; cb = b2;
                    }
                    if (b2 >= 0) a += __bfloat162float(sA[r * PAD + col]);
                }
                if (cb >= 0) atomicAdd(&g_aggM[(cb * C + c) * H + col], a);
            }
            if (tid >= 128 && tid < 131) {
                int d = tid - 128; float a = 0.f; int cb = sbid[0];
                for (int r = 0; r < TILE; r++) {
                    int b2 = sbid[r];
                    if (b2 != cb) {
                        if (cb >= 0) atomicAdd(&g_aggT[cb * 9 + d * 3 + c], a);
                        a = 0.f; cb = b2;
                    }
                    if (b2 >= 0) a += sdiff[r * 9 + c * 3 + d] * ssm[r];
                }
                if (cb >= 0) atomicAdd(&g_aggT[cb * 9 + d * 3 + c], a);
            }
            __syncthreads();
        }
    }
}

// ---------------------------------------------------------------------------
// finalize: node MLP on B*C rows (256 threads, split-K) + both outputs
// ---------------------------------------------------------------------------
__global__ void final_kernel(const float* __restrict__ vnf,
                             const float* __restrict__ vcoord,
                             const float* __restrict__ Wn1, const float* __restrict__ bn1,
                             const float* __restrict__ Wn2, const float* __restrict__ bn2,
                             float* __restrict__ out, int B) {
    __shared__ float s_in[2 * H];
    __shared__ float s_h1[H];
    __shared__ float s_p[2 * H];
    int tid = threadIdx.x;
    int b = blockIdx.x / C, c = blockIdx.x % C;

    float cnt = fmaxf(g_cnt[b], 1.0f);
    if (tid < 128) {
        s_in[tid]       = vnf[(b * NF + tid) * C + c];
        s_in[128 + tid] = g_aggM[(b * C + c) * H + tid] / cnt;
    }
    __syncthreads();
    {
        int col = tid & 127, half = tid >> 7;
        const float* w  = Wn1 + half * 128 * H;
        const float* xi = s_in + half * 128;
        float a0 = 0.f, a1 = 0.f, a2 = 0.f, a3 = 0.f;
#pragma unroll 8
        for (int k = 0; k < 128; k += 4) {
            a0 = fmaf(xi[k],     __ldg(&w[(k)     * H + col]), a0);
            a1 = fmaf(xi[k + 1], __ldg(&w[(k + 1) * H + col]), a1);
            a2 = fmaf(xi[k + 2], __ldg(&w[(k + 2) * H + col]), a2);
            a3 = fmaf(xi[k + 3], __ldg(&w[(k + 3) * H + col]), a3);
        }
        s_p[half * 128 + col] = (a0 + a1) + (a2 + a3);
    }
    __syncthreads();
    if (tid < 128) s_h1[tid] = silu_p(bn1[tid] + s_p[tid] + s_p[128 + tid]);
    __syncthreads();
    {
        int col = tid & 127, half = tid >> 7;
        float a0 = 0.f, a1 = 0.f, a2 = 0.f, a3 = 0.f;
#pragma unroll 8
        for (int k = 0; k < 64; k += 4) {
            int kk = half * 64 + k;
            a0 = fmaf(s_h1[kk],     __ldg(&Wn2[(kk)     * H + col]), a0);
            a1 = fmaf(s_h1[kk + 1], __ldg(&Wn2[(kk + 1) * H + col]), a1);
            a2 = fmaf(s_h1[kk + 2], __ldg(&Wn2[(kk + 2) * H + col]), a2);
            a3 = fmaf(s_h1[kk + 3], __ldg(&Wn2[(kk + 3) * H + col]), a3);
        }
        s_p[half * 128 + col] = (a0 + a1) + (a2 + a3);
    }
    __syncthreads();
    if (tid < 128)
        out[(b * NF + tid) * C + c] =
            vnf[(b * NF + tid) * C + c] + bn2[tid] + s_p[tid] + s_p[128 + tid];

    if (c == 0 && tid >= 128 && tid < 137) {
        int t = tid - 128;
        int d = t / 3, cc = t % 3;
        int idx = (b * 3 + d) * C + cc;
        out[B * NF * C + idx] = vcoord[idx] + g_aggT[idx] / cnt;
    }
}

// ---------------------------------------------------------------------------
extern "C" void kernel_launch(void* const* d_in, const int* in_sizes, int n_in,
                              void* d_out, int out_size) {
    const float* node_feat = (const float*)d_in[0];
    const float* coord     = (const float*)d_in[1];
    const float* vnf       = (const float*)d_in[2];
    const float* vcoord    = (const float*)d_in[3];
    const int*   batch     = (const int*)  d_in[4];
    const float* We1 = (const float*)d_in[5];
    const float* be1 = (const float*)d_in[6];
    const float* We2 = (const float*)d_in[7];
    const float* be2 = (const float*)d_in[8];
    const float* Wc1 = (const float*)d_in[9];
    const float* bc1 = (const float*)d_in[10];
    const float* Wc2 = (const float*)d_in[11];
    const float* Wn1 = (const float*)d_in[12];
    const float* bn1 = (const float*)d_in[13];
    const float* Wn2 = (const float*)d_in[14];
    const float* bn2 = (const float*)d_in[15];

    int N = in_sizes[0] / NF;
    int B = in_sizes[2] / (NF * C);

    cudaFuncSetAttribute(main_kernel,
                         cudaFuncAttributeMaxDynamicSharedMemorySize, SMEM_TOTAL);

    __nv_bfloat16* gW = nullptr;
    cudaGetSymbolAddress((void**)&gW, g_Wimg);

    prep_img<<<3 * 128, 128>>>(We1, We2, Wc1, gW);
    prep_V1<<<B * C, 128>>>(vnf, We1, be1);
    main_kernel<<<NBLK, THREADS, SMEM_TOTAL>>>(node_feat, coord, vcoord, batch,
                                               We1, be2, bc1, Wc2, N);
    final_kernel<<<B * C, 256>>>(vnf, vcoord, Wn1, bn1, Wn2, bn2,
                                 (float*)d_out, B);
}

// round 11
// speedup vs baseline: 1.2166x; 1.2166x over previous
#include <cuda_runtime.h>
#include <cuda_bf16.h>
#include <cuda_fp16.h>
#include <cstdint>

// EGCL_A2V — bf16 HMMA + ldmatrix, 192-row tiles (12 warps), dynamic tiles.
// Fast path (single-segment tile): warp-private pipeline, two __syncthreads
// per tile. Slow path: sync-heavy body. (R8-proven main; improved epilogues.)

#define NF 128
#define H  128
#define C  3
#define B_MAX 256
#define THREADS 384
#define NW 12
#define TILE 192
#define NBLK 148
#define PAD 136
#define WSTRIDE (128*PAD)

#define SMEM_SW 0
#define SMEM_SA 104448
#define SMEM_F  156672
#define SMEM_TOTAL 193280

// float-region layout
#define F_WR    0
#define F_BE2   128
#define F_BC1   256
#define F_WC2   384
#define F_SRAD  512          // [192][3]
#define F_SDIFF 1088         // [192][9]
#define F_SSM   2816         // [3][192]
#define F_SWP   3392         // [3][12][128]
#define F_SBID  8576         // int[192]

__device__ float g_V1[B_MAX * C * H];
__device__ float g_aggM[B_MAX * C * H];
__device__ float g_aggT[B_MAX * 9];
__device__ float g_cnt[B_MAX];
__device__ unsigned g_tile;
__device__ __align__(16) __nv_bfloat16 g_Wimg[3 * WSTRIDE];

// ---------------- helpers ----------------
__device__ __forceinline__ float silu_p(float x) { return x / (1.0f + __expf(-x)); }

__device__ __forceinline__ float2 silu2(float f0, float f1) {
    __half2 h  = __floats2half2_rn(f0, f1);
    __half2 hx = __hmul2(h, __float2half2_rn(0.5f));
    uint32_t hu = *reinterpret_cast<uint32_t*>(&hx);
    uint32_t tu;
    asm("tanh.approx.f16x2 %0, %1;" : "=r"(tu) : "r"(hu));
    __half2 t = *reinterpret_cast<__half2*>(&tu);
    __half2 s = __hfma2(hx, t, hx);
    return __half22float2(s);
}
__device__ __forceinline__ uint32_t pack_bf16(float lo, float hi) {
    uint32_t r;
    asm("cvt.rn.bf16x2.f32 %0, %1, %2;" : "=r"(r) : "f"(hi), "f"(lo));
    return r;
}
__device__ __forceinline__ uint32_t smem_u32(const void* p) {
    uint32_t a;
    asm("{ .reg .u64 t; cvta.to.shared.u64 t, %1; cvt.u32.u64 %0, t; }" : "=r"(a) : "l"(p));
    return a;
}
__device__ __forceinline__ void ldsm_x4(uint32_t* r, uint32_t addr) {
    asm volatile("ldmatrix.sync.aligned.m8n8.x4.shared.b16 {%0,%1,%2,%3}, [%4];"
                 : "=r"(r[0]), "=r"(r[1]), "=r"(r[2]), "=r"(r[3]) : "r"(addr));
}
__device__ __forceinline__ void mma16816(float* d,
        uint32_t a0, uint32_t a1, uint32_t a2, uint32_t a3,
        uint32_t b0, uint32_t b1) {
    asm volatile(
        "mma.sync.aligned.m16n8k16.row.col.f32.bf16.bf16.f32 "
        "{%0,%1,%2,%3}, {%4,%5,%6,%7}, {%8,%9}, {%0,%1,%2,%3};"
        : "+f"(d[0]), "+f"(d[1]), "+f"(d[2]), "+f"(d[3])
        : "r"(a0), "r"(a1), "r"(a2), "r"(a3), "r"(b0), "r"(b1));
}
__device__ __forceinline__ void gemm128(uint32_t aAddr, uint32_t bAddr, float* acc) {
#pragma unroll 2
    for (int ks = 0; ks < 8; ks++) {
        uint32_t A[4];
        ldsm_x4(A, aAddr + ks * 32);
#pragma unroll
        for (int ntp = 0; ntp < 8; ntp++) {
            uint32_t Bf[4];
            ldsm_x4(Bf, bAddr + ntp * (16 * PAD * 2) + ks * 32);
            mma16816(acc + ntp * 8,     A[0], A[1], A[2], A[3], Bf[0], Bf[1]);
            mma16816(acc + ntp * 8 + 4, A[0], A[1], A[2], A[3], Bf[2], Bf[3]);
        }
    }
}

// ---------------------------------------------------------------------------
__global__ void prep_img(const float* __restrict__ We1,
                         const float* __restrict__ We2,
                         const float* __restrict__ Wc1,
                         __nv_bfloat16* __restrict__ gW) {
    int w = blockIdx.x >> 7, k = blockIdx.x & 127, n = threadIdx.x;
    const float* W = (w == 0) ? We1 : (w == 1) ? We2 : Wc1;
    gW[w * WSTRIDE + n * PAD + k] = __float2bfloat16(W[k * H + n]);
}

// ---------------------------------------------------------------------------
__global__ void prep_V1(const float* __restrict__ vnf,
                        const float* __restrict__ We1,
                        const float* __restrict__ be1) {
    __shared__ float sv[NF];
    int h = threadIdx.x, bc = blockIdx.x;
    int b = bc / C, c = bc % C;
    sv[h] = vnf[(b * NF + h) * C + c];
    __syncthreads();
    const float* w = We1 + NF * H;
    float a0 = 0.f, a1 = 0.f, a2 = 0.f, a3 = 0.f;
    float a4 = 0.f, a5 = 0.f, a6 = 0.f, a7 = 0.f;
#pragma unroll 4
    for (int f = 0; f < NF; f += 8) {
        a0 = fmaf(sv[f],     __ldg(&w[(f)     * H + h]), a0);
        a1 = fmaf(sv[f + 1], __ldg(&w[(f + 1) * H + h]), a1);
        a2 = fmaf(sv[f + 2], __ldg(&w[(f + 2) * H + h]), a2);
        a3 = fmaf(sv[f + 3], __ldg(&w[(f + 3) * H + h]), a3);
        a4 = fmaf(sv[f + 4], __ldg(&w[(f + 4) * H + h]), a4);
        a5 = fmaf(sv[f + 5], __ldg(&w[(f + 5) * H + h]), a5);
        a6 = fmaf(sv[f + 6], __ldg(&w[(f + 6) * H + h]), a6);
        a7 = fmaf(sv[f + 7], __ldg(&w[(f + 7) * H + h]), a7);
    }
    g_V1[bc * H + h] = be1[h] + (((a0 + a1) + (a2 + a3)) + ((a4 + a5) + (a6 + a7)));
    g_aggM[bc * H + h] = 0.0f;
    if (bc == 0) {
        for (int i = h; i < B_MAX * 9; i += blockDim.x) g_aggT[i] = 0.0f;
        for (int i = h; i < B_MAX; i += blockDim.x) g_cnt[i] = 0.0f;
        if (h == 0) g_tile = 0u;
    }
}

// ---------------------------------------------------------------------------
__global__ void __launch_bounds__(THREADS, 1)
main_kernel(const float* __restrict__ node_feat,
            const float* __restrict__ coord,
            const float* __restrict__ vcoord,
            const int*   __restrict__ batch,
            const float* __restrict__ We1,
            const float* __restrict__ be2,
            const float* __restrict__ bc1,
            const float* __restrict__ Wc2,
            int N) {
    extern __shared__ __align__(16) char smem[];
    __nv_bfloat16* sW = (__nv_bfloat16*)(smem + SMEM_SW);
    __nv_bfloat16* sA = (__nv_bfloat16*)(smem + SMEM_SA);
    float* sf = (float*)(smem + SMEM_F);
    float* swr   = sf + F_WR;
    float* sbe2  = sf + F_BE2;
    float* sbc1  = sf + F_BC1;
    float* swc2  = sf + F_WC2;
    float* srad  = sf + F_SRAD;
    float* sdiff = sf + F_SDIFF;
    float* ssm   = sf + F_SSM;
    float* swp   = sf + F_SWP;
    int*   sbid  = (int*)(sf + F_SBID);
    __shared__ int s_tile;

    const int tid = threadIdx.x, lane = tid & 31, warp = tid >> 5;

    {   // weights -> smem
        const uint4* src = (const uint4*)g_Wimg;
        uint4* dst = (uint4*)sW;
        for (int i = tid; i < 3 * WSTRIDE * 2 / 16; i += THREADS) dst[i] = src[i];
    }
    if (tid < 128) {
        swr[tid]  = We1[256 * H + tid];
        sbe2[tid] = be2[tid];
        sbc1[tid] = bc1[tid];
        swc2[tid] = Wc2[tid];
    }
    __syncthreads();

    const uint32_t sA_u = smem_u32(sA);
    const uint32_t sW_u = smem_u32(sW);
    const uint32_t aAddr = sA_u +
        (((warp * 16 + (lane & 15)) * PAD + (lane >> 4) * 8) << 1);
    const uint32_t bRel =
        (((((lane >> 4) & 1) * 8 + (lane & 7)) * PAD + ((lane >> 3) & 1) * 8) << 1);
    const uint32_t bAddr0 = sW_u + bRel;
    const uint32_t bAddr1 = bAddr0 + WSTRIDE * 2;
    const uint32_t bAddr2 = bAddr1 + WSTRIDE * 2;
    const int r0 = warp * 16 + (lane >> 2), r1 = r0 + 8;

    const int ntiles = (N + TILE - 1) / TILE;
    for (;;) {
        if (tid == 0) s_tile = (int)atomicAdd(&g_tile, 1u);
        __syncthreads();                       // B1 (fences prev-tile agg too)
        const int t = s_tile;
        if (t >= ntiles) break;
        const int base = t * TILE;

        const bool tileFull = (base + TILE <= N);
        const int bFirst = __ldg(&batch[base]);
        const int bLast  = __ldg(&batch[min(base + TILE - 1, N - 1)]);
        const bool fast  = tileFull && (bFirst == bLast) && bFirst >= 0;
        const int b0t = bFirst < 0 ? 0 : bFirst;

        if (fast) {
            // ================= FAST PATH: warp-private, 2 CTA barriers ======
            {   // own-rows load
                int r = warp * 16 + (lane >> 1), cb = (lane & 1) * 64;
                int n = base + r;
                const float4* nf = (const float4*)(node_feat + (size_t)n * NF + cb);
                __nv_bfloat16* dst = sA + r * PAD + cb;
#pragma unroll
                for (int q = 0; q < 16; q++) {
                    float4 v = __ldg(&nf[q]);
                    *(uint32_t*)(dst + q * 4)     = pack_bf16(v.x, v.y);
                    *(uint32_t*)(dst + q * 4 + 2) = pack_bf16(v.z, v.w);
                }
                if (lane < 16) {   // geometry for own row warp*16+lane
                    int m = warp * 16 + lane, nn = base + m;
                    float cx = coord[nn * 3 + 0], cy = coord[nn * 3 + 1], cz = coord[nn * 3 + 2];
#pragma unroll
                    for (int cc = 0; cc < C; cc++) {
                        float dx = __ldg(&vcoord[(b0t * 3 + 0) * C + cc]) - cx;
                        float dy = __ldg(&vcoord[(b0t * 3 + 1) * C + cc]) - cy;
                        float dz = __ldg(&vcoord[(b0t * 3 + 2) * C + cc]) - cz;
                        sdiff[m * 9 + cc * 3 + 0] = dx;
                        sdiff[m * 9 + cc * 3 + 1] = dy;
                        sdiff[m * 9 + cc * 3 + 2] = dz;
                        srad[m * 3 + cc] = sqrtf(dx * dx + dy * dy + dz * dz);
                    }
                }
            }
            if (tid == 0) atomicAdd(&g_cnt[b0t], (float)TILE);
            __syncwarp();

            // GEMM1
            float x1[64];
#pragma unroll
            for (int i = 0; i < 64; i++) x1[i] = 0.f;
            gemm128(aAddr, bAddr0, x1);
            __syncwarp();

#pragma unroll 1
            for (int c = 0; c < C; c++) {
                // EpA
                float rad0 = srad[r0 * 3 + c], rad1 = srad[r1 * 3 + c];
                const float* v1p = g_V1 + (b0t * C + c) * H;
#pragma unroll
                for (int nt = 0; nt < 16; nt++) {
                    int c0 = nt * 8 + (lane & 3) * 2;
                    float2 vv = __ldg((const float2*)(v1p + c0));
                    float w0 = swr[c0], w1 = swr[c0 + 1];
                    float2 u0 = silu2(x1[nt * 4 + 0] + vv.x + rad0 * w0,
                                      x1[nt * 4 + 1] + vv.y + rad0 * w1);
                    float2 u1 = silu2(x1[nt * 4 + 2] + vv.x + rad1 * w0,
                                      x1[nt * 4 + 3] + vv.y + rad1 * w1);
                    *(uint32_t*)(sA + r0 * PAD + c0) = pack_bf16(u0.x, u0.y);
                    *(uint32_t*)(sA + r1 * PAD + c0) = pack_bf16(u1.x, u1.y);
                }
                __syncwarp();

                // GEMM2
                float acc[64];
#pragma unroll
                for (int i = 0; i < 64; i++) acc[i] = 0.f;
                gemm128(aAddr, bAddr1, acc);
                __syncwarp();

                // EpB: m2 -> sA; per-warp column sums -> swp[c][warp]
#pragma unroll
                for (int nt = 0; nt < 16; nt++) {
                    int c0 = nt * 8 + (lane & 3) * 2;
                    float2 u0 = silu2(acc[nt * 4 + 0] + sbe2[c0], acc[nt * 4 + 1] + sbe2[c0 + 1]);
                    float2 u1 = silu2(acc[nt * 4 + 2] + sbe2[c0], acc[nt * 4 + 3] + sbe2[c0 + 1]);
                    *(uint32_t*)(sA + r0 * PAD + c0) = pack_bf16(u0.x, u0.y);
                    *(uint32_t*)(sA + r1 * PAD + c0) = pack_bf16(u1.x, u1.y);
                    float v0 = u0.x + u1.x, v1 = u0.y + u1.y;
                    v0 += __shfl_xor_sync(0xffffffffu, v0, 4);
                    v0 += __shfl_xor_sync(0xffffffffu, v0, 8);
                    v0 += __shfl_xor_sync(0xffffffffu, v0, 16);
                    v1 += __shfl_xor_sync(0xffffffffu, v1, 4);
                    v1 += __shfl_xor_sync(0xffffffffu, v1, 8);
                    v1 += __shfl_xor_sync(0xffffffffu, v1, 16);
                    if (lane < 4) {
                        swp[(c * NW + warp) * 128 + c0]     = v0;
                        swp[(c * NW + warp) * 128 + c0 + 1] = v1;
                    }
                }
                __syncwarp();

                // GEMM3
#pragma unroll
                for (int i = 0; i < 64; i++) acc[i] = 0.f;
                gemm128(aAddr, bAddr2, acc);

                // EpC: row scalar s
                {
                    float s0 = 0.f, s1 = 0.f;
#pragma unroll
                    for (int nt = 0; nt < 16; nt++) {
                        int c0 = nt * 8 + (lane & 3) * 2;
                        float2 u0 = silu2(acc[nt * 4 + 0] + sbc1[c0], acc[nt * 4 + 1] + sbc1[c0 + 1]);
                        float2 u1 = silu2(acc[nt * 4 + 2] + sbc1[c0], acc[nt * 4 + 3] + sbc1[c0 + 1]);
                        s0 += u0.x * swc2[c0] + u0.y * swc2[c0 + 1];
                        s1 += u1.x * swc2[c0] + u1.y * swc2[c0 + 1];
                    }
                    s0 += __shfl_xor_sync(0xffffffffu, s0, 1);
                    s0 += __shfl_xor_sync(0xffffffffu, s0, 2);
                    s1 += __shfl_xor_sync(0xffffffffu, s1, 1);
                    s1 += __shfl_xor_sync(0xffffffffu, s1, 2);
                    if ((lane & 3) == 0) { ssm[c * TILE + r0] = s0; ssm[c * TILE + r1] = s1; }
                }
                __syncwarp();   // GEMM3 reads done before next EpA overwrites sA
            }

            __syncthreads();                   // B2: swp/ssm/sdiff visible

            // aggM: 128 cols x 3 channels
            if (tid < 128) {
#pragma unroll
                for (int c = 0; c < C; c++) {
                    float s = 0.f;
#pragma unroll
                    for (int w = 0; w < NW; w++) s += swp[(c * NW + w) * 128 + tid];
                    atomicAdd(&g_aggM[(b0t * C + c) * H + tid], s);
                }
            }
            // aggT: 9 (c,d) pairs by warps 0..8
            if (warp < 9) {
                int c = warp / 3, d = warp % 3;
                float v = 0.f;
#pragma unroll
                for (int q = 0; q < TILE / 32; q++) {
                    int r = lane + q * 32;
                    v += sdiff[r * 9 + c * 3 + d] * ssm[c * TILE + r];
                }
                v += __shfl_xor_sync(0xffffffffu, v, 16);
                v += __shfl_xor_sync(0xffffffffu, v, 8);
                v += __shfl_xor_sync(0xffffffffu, v, 4);
                v += __shfl_xor_sync(0xffffffffu, v, 2);
                v += __shfl_xor_sync(0xffffffffu, v, 1);
                if (lane == 0) atomicAdd(&g_aggT[b0t * 9 + d * 3 + c], v);
            }
            continue;   // loop-top B1 fences agg reads
        }

        // ================= SLOW PATH (segment boundary / tail) ==============
        if (tid < TILE) {
            int m = tid, n = base + m;
            bool valid = n < N;
            int nc = valid ? n : N - 1;
            int b = valid ? batch[n] : -1;
            sbid[m] = b;
            int bb = b < 0 ? 0 : b;
            float cx = coord[nc * 3 + 0], cy = coord[nc * 3 + 1], cz = coord[nc * 3 + 2];
#pragma unroll
            for (int cc = 0; cc < C; cc++) {
                float dx = __ldg(&vcoord[(bb * 3 + 0) * C + cc]) - cx;
                float dy = __ldg(&vcoord[(bb * 3 + 1) * C + cc]) - cy;
                float dz = __ldg(&vcoord[(bb * 3 + 2) * C + cc]) - cz;
                sdiff[m * 9 + cc * 3 + 0] = dx;
                sdiff[m * 9 + cc * 3 + 1] = dy;
                sdiff[m * 9 + cc * 3 + 2] = dz;
                srad[m * 3 + cc] = sqrtf(dx * dx + dy * dy + dz * dz);
            }
        }
        {
            int r = tid >> 1, cb = (tid & 1) * 64;
            int n = base + r;
            int nc = n < N ? n : N - 1;
            const float4* nf = (const float4*)(node_feat + (size_t)nc * NF + cb);
            __nv_bfloat16* dst = sA + r * PAD + cb;
#pragma unroll
            for (int q = 0; q < 16; q++) {
                float4 v = __ldg(&nf[q]);
                *(uint32_t*)(dst + q * 4)     = pack_bf16(v.x, v.y);
                *(uint32_t*)(dst + q * 4 + 2) = pack_bf16(v.z, v.w);
            }
        }
        __syncthreads();

        if (tid == 0) {
            int cb = sbid[0]; float cl = 0.f;
            for (int r = 0; r < TILE; r++) {
                int b2 = sbid[r];
                if (b2 != cb) { if (cb >= 0) atomicAdd(&g_cnt[cb], cl); cl = 0.f; cb = b2; }
                if (b2 >= 0) cl += 1.f;
            }
            if (cb >= 0) atomicAdd(&g_cnt[cb], cl);
        }

        int bb0 = sbid[r0]; bb0 = bb0 < 0 ? 0 : bb0;
        int bb1 = sbid[r1]; bb1 = bb1 < 0 ? 0 : bb1;

        float x1[64];
#pragma unroll
        for (int i = 0; i < 64; i++) x1[i] = 0.f;
        gemm128(aAddr, bAddr0, x1);
        __syncthreads();

#pragma unroll 1
        for (int c = 0; c < C; c++) {
            float rad0 = srad[r0 * 3 + c], rad1 = srad[r1 * 3 + c];
            const float* v0p = g_V1 + (bb0 * C + c) * H;
            const float* v1p = g_V1 + (bb1 * C + c) * H;
#pragma unroll
            for (int nt = 0; nt < 16; nt++) {
                int c0 = nt * 8 + (lane & 3) * 2;
                float w0 = swr[c0], w1 = swr[c0 + 1];
                float2 u0 = silu2(x1[nt * 4 + 0] + __ldg(&v0p[c0])     + rad0 * w0,
                                  x1[nt * 4 + 1] + __ldg(&v0p[c0 + 1]) + rad0 * w1);
                float2 u1 = silu2(x1[nt * 4 + 2] + __ldg(&v1p[c0])     + rad1 * w0,
                                  x1[nt * 4 + 3] + __ldg(&v1p[c0 + 1]) + rad1 * w1);
                *(uint32_t*)(sA + r0 * PAD + c0) = pack_bf16(u0.x, u0.y);
                *(uint32_t*)(sA + r1 * PAD + c0) = pack_bf16(u1.x, u1.y);
            }
            __syncthreads();

            float acc[64];
#pragma unroll
            for (int i = 0; i < 64; i++) acc[i] = 0.f;
            gemm128(aAddr, bAddr1, acc);
            __syncthreads();

#pragma unroll
            for (int nt = 0; nt < 16; nt++) {
                int c0 = nt * 8 + (lane & 3) * 2;
                float2 u0 = silu2(acc[nt * 4 + 0] + sbe2[c0], acc[nt * 4 + 1] + sbe2[c0 + 1]);
                float2 u1 = silu2(acc[nt * 4 + 2] + sbe2[c0], acc[nt * 4 + 3] + sbe2[c0 + 1]);
                *(uint32_t*)(sA + r0 * PAD + c0) = pack_bf16(u0.x, u0.y);
                *(uint32_t*)(sA + r1 * PAD + c0) = pack_bf16(u1.x, u1.y);
            }
            __syncthreads();

#pragma unroll
            for (int i = 0; i < 64; i++) acc[i] = 0.f;
            gemm128(aAddr, bAddr2, acc);

            {
                float s0 = 0.f, s1 = 0.f;
#pragma unroll
                for (int nt = 0; nt < 16; nt++) {
                    int c0 = nt * 8 + (lane & 3) * 2;
                    float2 u0 = silu2(acc[nt * 4 + 0] + sbc1[c0], acc[nt * 4 + 1] + sbc1[c0 + 1]);
                    float2 u1 = silu2(acc[nt * 4 + 2] + sbc1[c0], acc[nt * 4 + 3] + sbc1[c0 + 1]);
                    s0 += u0.x * swc2[c0] + u0.y * swc2[c0 + 1];
                    s1 += u1.x * swc2[c0] + u1.y * swc2[c0 + 1];
                }
                s0 += __shfl_xor_sync(0xffffffffu, s0, 1);
                s0 += __shfl_xor_sync(0xffffffffu, s0, 2);
                s1 += __shfl_xor_sync(0xffffffffu, s1, 1);
                s1 += __shfl_xor_sync(0xffffffffu, s1, 2);
                if ((lane & 3) == 0) { ssm[r0] = s0; ssm[r1] = s1; }
            }
            __syncthreads();

            if (tid < 128) {
                int col = tid; float a = 0.f; int cb = sbid[0];
                for (int r = 0; r < TILE; r++) {
                    int b2 = sbid[r];
                    if (b2 != cb) {
                        if (cb >= 0) atomicAdd(&g_aggM[(cb * C + c) * H + col], a);
                        a = 0.f; cb = b2;
                    }
                    if (b2 >= 0) a += __bfloat162float(sA[r * PAD + col]);
                }
                if (cb >= 0) atomicAdd(&g_aggM[(cb * C + c) * H + col], a);
            }
            if (tid >= 128 && tid < 131) {
                int d = tid - 128; float a = 0.f; int cb = sbid[0];
                for (int r = 0; r < TILE; r++) {
                    int b2 = sbid[r];
                    if (b2 != cb) {
                        if (cb >= 0) atomicAdd(&g_aggT[cb * 9 + d * 3 + c], a);
                        a = 0.f; cb = b2;
                    }
                    if (b2 >= 0) a += sdiff[r * 9 + c * 3 + d] * ssm[r];
                }
                if (cb >= 0) atomicAdd(&g_aggT[cb * 9 + d * 3 + c], a);
            }
            __syncthreads();
        }
    }
}

// ---------------------------------------------------------------------------
// finalize: node MLP on B*C rows, split-K, 8-way MLP per thread
// ---------------------------------------------------------------------------
__global__ void final_kernel(const float* __restrict__ vnf,
                             const float* __restrict__ vcoord,
                             const float* __restrict__ Wn1, const float* __restrict__ bn1,
                             const float* __restrict__ Wn2, const float* __restrict__ bn2,
                             float* __restrict__ out, int B) {
    __shared__ float s_in[2 * H];
    __shared__ float s_h1[H];
    __shared__ float s_p[2 * H];
    int tid = threadIdx.x;
    int b = blockIdx.x / C, c = blockIdx.x % C;

    float cnt = fmaxf(g_cnt[b], 1.0f);
    if (tid < 128) {
        s_in[tid]       = vnf[(b * NF + tid) * C + c];
        s_in[128 + tid] = g_aggM[(b * C + c) * H + tid] / cnt;
    }
    __syncthreads();
    {
        int col = tid & 127, half = tid >> 7;
        const float* w  = Wn1 + half * 128 * H;
        const float* xi = s_in + half * 128;
        float a0 = 0.f, a1 = 0.f, a2 = 0.f, a3 = 0.f;
        float a4 = 0.f, a5 = 0.f, a6 = 0.f, a7 = 0.f;
#pragma unroll 16
        for (int k = 0; k < 128; k += 8) {
            a0 = fmaf(xi[k],     __ldg(&w[(k)     * H + col]), a0);
            a1 = fmaf(xi[k + 1], __ldg(&w[(k + 1) * H + col]), a1);
            a2 = fmaf(xi[k + 2], __ldg(&w[(k + 2) * H + col]), a2);
            a3 = fmaf(xi[k + 3], __ldg(&w[(k + 3) * H + col]), a3);
            a4 = fmaf(xi[k + 4], __ldg(&w[(k + 4) * H + col]), a4);
            a5 = fmaf(xi[k + 5], __ldg(&w[(k + 5) * H + col]), a5);
            a6 = fmaf(xi[k + 6], __ldg(&w[(k + 6) * H + col]), a6);
            a7 = fmaf(xi[k + 7], __ldg(&w[(k + 7) * H + col]), a7);
        }
        s_p[half * 128 + col] = (((a0 + a1) + (a2 + a3)) + ((a4 + a5) + (a6 + a7)));
    }
    __syncthreads();
    if (tid < 128) s_h1[tid] = silu_p(bn1[tid] + s_p[tid] + s_p[128 + tid]);
    __syncthreads();
    {
        int col = tid & 127, half = tid >> 7;
        const float* hi = s_h1 + half * 64;
        const float* w  = Wn2 + half * 64 * H;
        float a0 = 0.f, a1 = 0.f, a2 = 0.f, a3 = 0.f;
        float a4 = 0.f, a5 = 0.f, a6 = 0.f, a7 = 0.f;
#pragma unroll 8
        for (int k = 0; k < 64; k += 8) {
            a0 = fmaf(hi[k],     __ldg(&w[(k)     * H + col]), a0);
            a1 = fmaf(hi[k + 1], __ldg(&w[(k + 1) * H + col]), a1);
            a2 = fmaf(hi[k + 2], __ldg(&w[(k + 2) * H + col]), a2);
            a3 = fmaf(hi[k + 3], __ldg(&w[(k + 3) * H + col]), a3);
            a4 = fmaf(hi[k + 4], __ldg(&w[(k + 4) * H + col]), a4);
            a5 = fmaf(hi[k + 5], __ldg(&w[(k + 5) * H + col]), a5);
            a6 = fmaf(hi[k + 6], __ldg(&w[(k + 6) * H + col]), a6);
            a7 = fmaf(hi[k + 7], __ldg(&w[(k + 7) * H + col]), a7);
        }
        s_p[half * 128 + col] = (((a0 + a1) + (a2 + a3)) + ((a4 + a5) + (a6 + a7)));
    }
    __syncthreads();
    if (tid < 128)
        out[(b * NF + tid) * C + c] =
            vnf[(b * NF + tid) * C + c] + bn2[tid] + s_p[tid] + s_p[128 + tid];

    if (c == 0 && tid >= 128 && tid < 137) {
        int t = tid - 128;
        int d = t / 3, cc = t % 3;
        int idx = (b * 3 + d) * C + cc;
        out[B * NF * C + idx] = vcoord[idx] + g_aggT[idx] / cnt;
    }
}

// ---------------------------------------------------------------------------
extern "C" void kernel_launch(void* const* d_in, const int* in_sizes, int n_in,
                              void* d_out, int out_size) {
    const float* node_feat = (const float*)d_in[0];
    const float* coord     = (const float*)d_in[1];
    const float* vnf       = (const float*)d_in[2];
    const float* vcoord    = (const float*)d_in[3];
    const int*   batch     = (const int*)  d_in[4];
    const float* We1 = (const float*)d_in[5];
    const float* be1 = (const float*)d_in[6];
    const float* We2 = (const float*)d_in[7];
    const float* be2 = (const float*)d_in[8];
    const float* Wc1 = (const float*)d_in[9];
    const float* bc1 = (const float*)d_in[10];
    const float* Wc2 = (const float*)d_in[11];
    const float* Wn1 = (const float*)d_in[12];
    const float* bn1 = (const float*)d_in[13];
    const float* Wn2 = (const float*)d_in[14];
    const float* bn2 = (const float*)d_in[15];

    int N = in_sizes[0] / NF;
    int B = in_sizes[2] / (NF * C);

    cudaFuncSetAttribute(main_kernel,
                         cudaFuncAttributeMaxDynamicSharedMemorySize, SMEM_TOTAL);

    __nv_bfloat16* gW = nullptr;
    cudaGetSymbolAddress((void**)&gW, g_Wimg);

    prep_img<<<3 * 128, 128>>>(We1, We2, Wc1, gW);
    prep_V1<<<B * C, 128>>>(vnf, We1, be1);
    main_kernel<<<NBLK, THREADS, SMEM_TOTAL>>>(node_feat, coord, vcoord, batch,
                                               We1, be2, bc1, Wc2, N);
    final_kernel<<<B * C, 256>>>(vnf, vcoord, Wn1, bn1, Wn2, bn2,
                                 (float*)d_out, B);
}